// round 5
// baseline (speedup 1.0000x reference)
#include <cuda_runtime.h>
#include <float.h>

// ROI max pool, two-phase:
//  1) transpose features [2,256,50,50] -> channel-last scratch [2,50,50,256]
//  2) pool: block = (roi, 128-ch group, i-row); 7 warps (one j bin each);
//     lane = 4 consecutive channels (float4). Bin width <= 8 is fully
//     unrolled with min-clamped addresses -> 4-8 independent loads in
//     flight per row (attacks the latency-exposure bottleneck).

#define OUTP 7
#define NBINS 49
#define CCH  256
#define HH   50
#define WW   50
#define HWSZ (HH * WW)
#define BB   2
#define CS   (CCH / 4)   // float4 stride between spatial positions

__device__ __align__(16) float g_feat_t[BB * HWSZ * CCH];   // [b][hw][c]

// ---------------- transpose: [b][c][hw] -> [b][hw][c] ----------------
__global__ void transpose_kernel(const float* __restrict__ feat)
{
    __shared__ float tile[32][33];
    int b   = blockIdx.z;
    int hw0 = blockIdx.x * 32;
    int c0  = blockIdx.y * 32;

    int hw_r = hw0 + threadIdx.x;
    #pragma unroll
    for (int r = threadIdx.y; r < 32; r += 8) {
        if (hw_r < HWSZ)
            tile[r][threadIdx.x] = feat[((size_t)b * CCH + c0 + r) * HWSZ + hw_r];
    }
    __syncthreads();
    #pragma unroll
    for (int r = threadIdx.y; r < 32; r += 8) {
        int hw_w = hw0 + r;
        if (hw_w < HWSZ)
            g_feat_t[((size_t)b * HWSZ + hw_w) * CCH + c0 + threadIdx.x] =
                tile[threadIdx.x][r];
    }
}

__device__ __forceinline__ float4 fmax4(float4 a, float4 b)
{
    return make_float4(fmaxf(a.x, b.x), fmaxf(a.y, b.y),
                       fmaxf(a.z, b.z), fmaxf(a.w, b.w));
}

// ---------------- pooling ----------------
// grid: 128 rois * 2 ch-groups * 7 i = 1792 blocks; 224 threads = 7 warps.
#define SPITCH 132
__global__ __launch_bounds__(224) void roi_pool_kernel(
    const float* __restrict__ rois, float* __restrict__ out)
{
    __shared__ float s[OUTP * SPITCH];

    int bi = blockIdx.x;
    int i  = bi % OUTP;
    int cg = (bi / OUTP) & 1;            // channels [cg*128, +128)
    int n  = bi / (OUTP * 2);

    int lane = threadIdx.x & 31;
    int j    = threadIdx.x >> 5;         // warp id = bin column

    const float* r = rois + n * 5;
    int im = (int)rintf(r[0]);
    int x1 = (int)rintf(r[1] * 0.0625f);
    int y1 = (int)rintf(r[2] * 0.0625f);
    int x2 = (int)rintf(r[3] * 0.0625f);
    int y2 = (int)rintf(r[4] * 0.0625f);
    int h  = y2 - y1 + 1;
    int w  = x2 - x1 + 1;

    int ys = i * h / OUTP + y1;
    int ye = ((i + 1) * h + OUTP - 1) / OUTP + y1;
    int xs = j * w / OUTP + x1;
    int xe = ((j + 1) * w + OUTP - 1) / OUTP + x1;
    ys = max(ys, 0);  xs = max(xs, 0);
    ye = min(ye, HH); xe = min(xe, WW);

    int wm1 = xe - xs - 1;               // 0..7, uniform across warp

    const float4* base = (const float4*)
        (g_feat_t + (size_t)im * HWSZ * CCH + cg * 128 + lane * 4);

    float4 acc = make_float4(-FLT_MAX, -FLT_MAX, -FLT_MAX, -FLT_MAX);
    for (int y = ys; y < ye; ++y) {
        const float4* row = base + (size_t)(y * WW + xs) * CS;
        // 4 independent loads, min-clamped (dup loads harmless for max)
        float4 v0 = __ldg(row);
        float4 v1 = __ldg(row + min(1, wm1) * CS);
        float4 v2 = __ldg(row + min(2, wm1) * CS);
        float4 v3 = __ldg(row + min(3, wm1) * CS);
        float4 m0 = fmax4(v0, v1);
        float4 m1 = fmax4(v2, v3);
        if (wm1 >= 4) {                  // warp-uniform branch
            float4 v4 = __ldg(row + 4 * CS);
            float4 v5 = __ldg(row + min(5, wm1) * CS);
            float4 v6 = __ldg(row + min(6, wm1) * CS);
            float4 v7 = __ldg(row + min(7, wm1) * CS);
            m0 = fmax4(m0, fmax4(v4, v5));
            m1 = fmax4(m1, fmax4(v6, v7));
        }
        acc = fmax4(acc, fmax4(m0, m1));
    }

    *(float4*)&s[j * SPITCH + lane * 4] = acc;
    __syncthreads();

    // out[n][cg*128 + c][i*7 + j]: 128 runs of 7 contiguous floats.
    float* outb = out + ((size_t)n * CCH + cg * 128) * NBINS + i * OUTP;
    #pragma unroll
    for (int idx = threadIdx.x; idx < 128 * OUTP; idx += 224) {
        int c  = idx / OUTP;
        int jj = idx - c * OUTP;
        outb[(size_t)c * NBINS + jj] = s[jj * SPITCH + c];
    }
}

extern "C" void kernel_launch(void* const* d_in, const int* in_sizes, int n_in,
                              void* d_out, int out_size)
{
    const float* feat = (const float*)d_in[0];
    const float* rois = (const float*)d_in[1];
    float* out = (float*)d_out;

    dim3 tgrid((HWSZ + 31) / 32, CCH / 32, BB);
    dim3 tblk(32, 8);
    transpose_kernel<<<tgrid, tblk>>>(feat);

    roi_pool_kernel<<<128 * 2 * OUTP, 224>>>(rois, out);
}